// round 6
// baseline (speedup 1.0000x reference)
#include <cuda_runtime.h>
#include <cuda_fp16.h>
#include <math.h>
#include <stdint.h>

// Problem constants
#define B_WIN   2048
#define N_TOK   64
#define DIM     512
#define HEADS   16
#define DH      32
#define QKV_DIM 1536
#define WIN     8
#define REL_SZ  15
#define M_ROWS  (B_WIN * N_TOK)   // 131072

// Scratch (no cudaMalloc allowed)
__device__ float  g_qkv[(size_t)M_ROWS * QKV_DIM];     // fp32 qkv for attention
__device__ __half g_xh[(size_t)M_ROWS * DIM];          // x, fp16
__device__ __half g_atth[(size_t)M_ROWS * DIM];        // attention out, fp16
__device__ __half g_wqkv_t[(size_t)QKV_DIM * DIM];     // w_qkv^T [N,K], fp16
__device__ __half g_wproj_t[(size_t)DIM * DIM];        // w_proj^T [N,K], fp16

__device__ __forceinline__ uint32_t smem_u32(const void* p) {
    uint32_t a;
    asm("{ .reg .u64 t; cvta.to.shared.u64 t, %1; cvt.u32.u64 %0, t; }" : "=r"(a) : "l"(p));
    return a;
}

__device__ __forceinline__ void cp_async16(uint32_t smem_dst, const void* gmem_src) {
    asm volatile("cp.async.cg.shared.global [%0], [%1], 16;\n" :: "r"(smem_dst), "l"(gmem_src));
}

// ---------------------------------------------------------------------------
// Pre-pass: fp32 -> fp16
// ---------------------------------------------------------------------------
__global__ void cvt_f32_h(const float4* __restrict__ in, __half2* __restrict__ out, int n4)
{
    for (int i = blockIdx.x * blockDim.x + threadIdx.x; i < n4; i += gridDim.x * blockDim.x) {
        float4 v = in[i];
        out[i * 2 + 0] = __floats2half2_rn(v.x, v.y);
        out[i * 2 + 1] = __floats2half2_rn(v.z, v.w);
    }
}

// Transpose + cvt: in[K][N] fp32 -> out[N][K] fp16
__global__ void transpose_h(const float* __restrict__ in, __half* __restrict__ out,
                            int K, int N)
{
    __shared__ float t[32][33];
    const int k0 = blockIdx.y * 32, n0 = blockIdx.x * 32;
    const int tx = threadIdx.x, ty = threadIdx.y;   // 32 x 8
    #pragma unroll
    for (int r = 0; r < 4; r++)
        t[ty + r * 8][tx] = in[(size_t)(k0 + ty + r * 8) * N + n0 + tx];
    __syncthreads();
    #pragma unroll
    for (int r = 0; r < 4; r++)
        out[(size_t)(n0 + ty + r * 8) * K + k0 + tx] = __float2half_rn(t[tx][ty + r * 8]);
}

// ---------------------------------------------------------------------------
// FP16 tensor-core GEMM: C[M,N] = A[M,K] @ Bt[N,K]^T + bias[N]   (fp32 accum)
// BM=128, BN=128, BK=32 halves. 8 warps (2x4), warp tile 64x32.
// mma.sync.m16n8k16.f16, ldmatrix fragment loads, 3-stage cp.async.
// ---------------------------------------------------------------------------
#define GBM 128
#define GBN 128
#define GBK 32
#define HPAD 8
#define ROWH (GBK + HPAD)                  // 40 halves = 80B row stride
#define TILE_H (GBM * ROWH)                // 5120 halves per tile
#define STAGE_H (2 * TILE_H)               // A + B
#define GEMM_SMEM (3 * STAGE_H * 2)        // 61440 bytes

__device__ __forceinline__ void ldsm_x4(uint32_t addr, uint32_t& r0, uint32_t& r1,
                                        uint32_t& r2, uint32_t& r3) {
    asm volatile("ldmatrix.sync.aligned.m8n8.x4.shared.b16 {%0,%1,%2,%3}, [%4];"
                 : "=r"(r0), "=r"(r1), "=r"(r2), "=r"(r3) : "r"(addr));
}

__global__ __launch_bounds__(256, 2)
void gemm_h(const __half* __restrict__ A, const __half* __restrict__ Bt,
            const float* __restrict__ bias, float* __restrict__ C,
            int M, int N, int K)
{
    extern __shared__ __half sm[];
    // stage s: A at sm + s*STAGE_H, B at + TILE_H

    const int tid  = threadIdx.x;
    const int warp = tid >> 5;
    const int lane = tid & 31;
    const int wm = warp & 1;               // 64-row half
    const int wn = warp >> 1;              // 32-col quarter
    const int g  = lane >> 2;
    const int t  = lane & 3;

    const int cm = blockIdx.y * GBM;
    const int cn = blockIdx.x * GBN;

    // global->smem: each thread 2x cp.async per tile: row = tid>>1, 32B seg = tid&1
    const int lrow = tid >> 1;
    const int lseg = (tid & 1) * 16;       // halves offset (16 halves = 32B)

    const __half* Abase = A + (size_t)(cm + lrow) * K + lseg;
    const __half* Bbase = Bt + (size_t)(cn + lrow) * K + lseg;

    const uint32_t smb = smem_u32(sm);

    float acc[4][4][4];
    #pragma unroll
    for (int i = 0; i < 4; i++)
        #pragma unroll
        for (int j = 0; j < 4; j++)
            #pragma unroll
            for (int r = 0; r < 4; r++)
                acc[i][j][r] = 0.0f;

    const int KT = K / GBK;                // 16

    auto fill = [&](int kt, int st) {
        const uint32_t sa = smb + (st * STAGE_H + lrow * ROWH + lseg) * 2;
        const uint32_t sb = sa + TILE_H * 2;
        const int k0 = kt * GBK;
        cp_async16(sa,      Abase + k0);
        cp_async16(sa + 16, Abase + k0 + 8);
        cp_async16(sb,      Bbase + k0);
        cp_async16(sb + 16, Bbase + k0 + 8);
        asm volatile("cp.async.commit_group;\n");
    };

    fill(0, 0);
    fill(1, 1);

    // per-lane ldmatrix address pieces
    const int lgrp = lane >> 3;            // 0..3
    const int lr   = lane & 7;
    // A: matrices (rows+0,k+0),(rows+8,k+0),(rows+0,k+8),(rows+8,k+8)
    const int a_row_add = (lgrp & 1) * 8 + lr;
    const int a_k_add   = (lgrp & 2) * 4;
    // B: matrices (n+0,k+0),(n+0,k+8),(n+8,k+0),(n+8,k+8)
    const int b_row_add = (lgrp >> 1) * 8 + lr;
    const int b_k_add   = (lgrp & 1) * 8;

    for (int kt = 0; kt < KT; kt++) {
        const int st = kt % 3;
        if (kt == KT - 1) {
            asm volatile("cp.async.wait_group 0;\n");
        } else {
            asm volatile("cp.async.wait_group 1;\n");
        }
        __syncthreads();

        if (kt + 2 < KT) fill(kt + 2, (kt + 2) % 3);

        const uint32_t sa = smb + (st * STAGE_H) * 2;
        const uint32_t sb = sa + TILE_H * 2;

        #pragma unroll
        for (int ks = 0; ks < 2; ks++) {
            const int k16 = ks * 16;
            uint32_t af[4][4];
            #pragma unroll
            for (int mt = 0; mt < 4; mt++) {
                const int row = wm * 64 + mt * 16 + a_row_add;
                ldsm_x4(sa + (row * ROWH + k16 + a_k_add) * 2,
                        af[mt][0], af[mt][1], af[mt][2], af[mt][3]);
            }
            uint32_t bf[4][2];
            #pragma unroll
            for (int np = 0; np < 2; np++) {
                const int row = wn * 32 + np * 16 + b_row_add;
                ldsm_x4(sb + (row * ROWH + k16 + b_k_add) * 2,
                        bf[np * 2][0], bf[np * 2][1], bf[np * 2 + 1][0], bf[np * 2 + 1][1]);
            }
            #pragma unroll
            for (int mt = 0; mt < 4; mt++)
                #pragma unroll
                for (int nt = 0; nt < 4; nt++) {
                    asm volatile(
                        "mma.sync.aligned.m16n8k16.row.col.f32.f16.f16.f32 "
                        "{%0,%1,%2,%3}, {%4,%5,%6,%7}, {%8,%9}, {%0,%1,%2,%3};\n"
                        : "+f"(acc[mt][nt][0]), "+f"(acc[mt][nt][1]),
                          "+f"(acc[mt][nt][2]), "+f"(acc[mt][nt][3])
                        : "r"(af[mt][0]), "r"(af[mt][1]), "r"(af[mt][2]), "r"(af[mt][3]),
                          "r"(bf[nt][0]), "r"(bf[nt][1]));
                }
        }
        __syncthreads();
    }

    // epilogue: add bias, store fp32
    #pragma unroll
    for (int mt = 0; mt < 4; mt++) {
        const size_t r0 = (size_t)cm + wm * 64 + mt * 16 + g;
        #pragma unroll
        for (int nt = 0; nt < 4; nt++) {
            const int col = cn + wn * 32 + nt * 8 + 2 * t;
            const float2 bv = *reinterpret_cast<const float2*>(bias + col);
            float2 o0, o1;
            o0.x = acc[mt][nt][0] + bv.x;
            o0.y = acc[mt][nt][1] + bv.y;
            o1.x = acc[mt][nt][2] + bv.x;
            o1.y = acc[mt][nt][3] + bv.y;
            *reinterpret_cast<float2*>(C + r0 * N + col)       = o0;
            *reinterpret_cast<float2*>(C + (r0 + 8) * N + col) = o1;
        }
    }
}

// ---------------------------------------------------------------------------
// Attention: one block per (window b, head h), 64 threads.
// fp32 math; writes fp16 output for the proj GEMM.
// ---------------------------------------------------------------------------
#define PADW 36

__global__ __launch_bounds__(64)
void attn_kernel(const float* __restrict__ rel)
{
    const int b = blockIdx.x;
    const int h = blockIdx.y;
    const int tid = threadIdx.x;

    __shared__ float qs[N_TOK][PADW];
    __shared__ float ks[N_TOK][PADW];
    __shared__ float vs[N_TOK][PADW];
    __shared__ __half os[N_TOK][DH];
    __shared__ float rels[REL_SZ * REL_SZ];

    const float* gq = g_qkv + (size_t)b * N_TOK * QKV_DIM + h * DH;

    for (int idx = tid; idx < N_TOK * 8; idx += 64) {
        const int m = idx >> 3;
        const int c = (idx & 7) * 4;
        const float* p = gq + (size_t)m * QKV_DIM + c;
        *reinterpret_cast<float4*>(&qs[m][c]) = *reinterpret_cast<const float4*>(p);
        *reinterpret_cast<float4*>(&ks[m][c]) = *reinterpret_cast<const float4*>(p + 512);
        *reinterpret_cast<float4*>(&vs[m][c]) = *reinterpret_cast<const float4*>(p + 1024);
    }
    for (int p = tid; p < REL_SZ * REL_SZ; p += 64) rels[p] = rel[h * REL_SZ * REL_SZ + p];
    __syncthreads();

    const int i = tid;
    const float scale = 0.17677669529663687f;
    float q[DH];
    #pragma unroll
    for (int d = 0; d < DH; d++) q[d] = qs[i][d] * scale;

    const int yi = i >> 3, xi = i & 7;

    float sc[N_TOK];
    float mx = -1e30f;
    #pragma unroll
    for (int j = 0; j < N_TOK; j++) {
        float s0 = 0.f, s1 = 0.f, s2 = 0.f, s3 = 0.f;
        #pragma unroll
        for (int d = 0; d < DH; d += 4) {
            const float4 kk = *reinterpret_cast<const float4*>(&ks[j][d]);
            s0 = fmaf(q[d + 0], kk.x, s0);
            s1 = fmaf(q[d + 1], kk.y, s1);
            s2 = fmaf(q[d + 2], kk.z, s2);
            s3 = fmaf(q[d + 3], kk.w, s3);
        }
        const int yj = j >> 3, xj = j & 7;
        const float s = (s0 + s1) + (s2 + s3) + rels[(yi - yj + 7) * REL_SZ + (xi - xj + 7)];
        sc[j] = s;
        mx = fmaxf(mx, s);
    }

    float sum = 0.0f;
    #pragma unroll
    for (int j = 0; j < N_TOK; j++) {
        const float e = __expf(sc[j] - mx);
        sc[j] = e;
        sum += e;
    }
    const float inv = 1.0f / sum;

    float out[DH];
    #pragma unroll
    for (int d = 0; d < DH; d++) out[d] = 0.0f;
    #pragma unroll
    for (int j = 0; j < N_TOK; j++) {
        const float p = sc[j];
        #pragma unroll
        for (int d = 0; d < DH; d += 4) {
            const float4 vv = *reinterpret_cast<const float4*>(&vs[j][d]);
            out[d + 0] = fmaf(p, vv.x, out[d + 0]);
            out[d + 1] = fmaf(p, vv.y, out[d + 1]);
            out[d + 2] = fmaf(p, vv.z, out[d + 2]);
            out[d + 3] = fmaf(p, vv.w, out[d + 3]);
        }
    }

    #pragma unroll
    for (int d = 0; d < DH; d += 2)
        *reinterpret_cast<__half2*>(&os[i][d]) =
            __floats2half2_rn(out[d] * inv, out[d + 1] * inv);
    __syncthreads();

    // coalesced half store: 64 rows x 64B regions = 256 x 16B chunks
    __half* go = g_atth + (size_t)b * N_TOK * DIM + h * DH;
    for (int idx = tid; idx < N_TOK * 4; idx += 64) {
        const int m = idx >> 2;
        const int c = (idx & 3) * 8;
        *reinterpret_cast<uint4*>(go + (size_t)m * DIM + c) =
            *reinterpret_cast<const uint4*>(&os[m][c]);
    }
}

// ---------------------------------------------------------------------------
// Launch
// ---------------------------------------------------------------------------
extern "C" void kernel_launch(void* const* d_in, const int* in_sizes, int n_in,
                              void* d_out, int out_size)
{
    const float* x      = (const float*)d_in[0];
    const float* w_qkv  = (const float*)d_in[1];
    const float* b_qkv  = (const float*)d_in[2];
    const float* rel    = (const float*)d_in[3];
    const float* w_proj = (const float*)d_in[4];
    const float* b_proj = (const float*)d_in[5];
    float* out = (float*)d_out;
    (void)in_sizes; (void)n_in; (void)out_size;

    float *qkv;
    __half *xh, *atth, *wqkvt, *wprojt;
    cudaGetSymbolAddress((void**)&qkv,    g_qkv);
    cudaGetSymbolAddress((void**)&xh,     g_xh);
    cudaGetSymbolAddress((void**)&atth,   g_atth);
    cudaGetSymbolAddress((void**)&wqkvt,  g_wqkv_t);
    cudaGetSymbolAddress((void**)&wprojt, g_wproj_t);

    cudaFuncSetAttribute(gemm_h, cudaFuncAttributeMaxDynamicSharedMemorySize, GEMM_SMEM);

    // 0) Convert x to fp16; transpose+convert weights to [N,K] fp16
    cvt_f32_h<<<4096, 256>>>((const float4*)x, (__half2*)xh, (M_ROWS * DIM) / 4);
    {
        dim3 blk(32, 8);
        transpose_h<<<dim3(QKV_DIM / 32, DIM / 32), blk>>>(w_qkv, wqkvt, DIM, QKV_DIM);
        transpose_h<<<dim3(DIM / 32, DIM / 32),     blk>>>(w_proj, wprojt, DIM, DIM);
    }

    // 1) QKV GEMM: [131072,512] @ [512,1536] + b_qkv  -> fp32
    {
        dim3 grid(QKV_DIM / GBN, M_ROWS / GBM);   // (12, 1024)
        gemm_h<<<grid, 256, GEMM_SMEM>>>(xh, wqkvt, b_qkv, qkv, M_ROWS, QKV_DIM, DIM);
    }

    // 2) Windowed attention (fp32 math, writes fp16 g_atth)
    {
        dim3 grid(B_WIN, HEADS);
        attn_kernel<<<grid, 64>>>(rel);
    }

    // 3) Output projection: [131072,512] @ [512,512] + b_proj -> fp32
    {
        dim3 grid(DIM / GBN, M_ROWS / GBM);       // (4, 1024)
        gemm_h<<<grid, 256, GEMM_SMEM>>>(atth, wprojt, b_proj, out, M_ROWS, DIM, DIM);
    }
}

// round 7
// speedup vs baseline: 1.6437x; 1.6437x over previous
#include <cuda_runtime.h>
#include <cuda_fp16.h>
#include <math.h>
#include <stdint.h>

// Problem constants
#define B_WIN   2048
#define N_TOK   64
#define DIM     512
#define HEADS   16
#define DH      32
#define QKV_DIM 1536
#define WIN     8
#define REL_SZ  15
#define M_ROWS  (B_WIN * N_TOK)   // 131072

// Scratch (no cudaMalloc allowed)
__device__ __half g_qkvh[(size_t)M_ROWS * QKV_DIM];    // qkv, fp16 (q pre-scaled)
__device__ __half g_xh[(size_t)M_ROWS * DIM];          // x, fp16
__device__ __half g_atth[(size_t)M_ROWS * DIM];        // attention out, fp16
__device__ __half g_wqkv_t[(size_t)QKV_DIM * DIM];     // w_qkv^T [N,K], fp16
__device__ __half g_wproj_t[(size_t)DIM * DIM];        // w_proj^T [N,K], fp16

__device__ __forceinline__ uint32_t smem_u32(const void* p) {
    uint32_t a;
    asm("{ .reg .u64 t; cvta.to.shared.u64 t, %1; cvt.u32.u64 %0, t; }" : "=r"(a) : "l"(p));
    return a;
}

__device__ __forceinline__ void cp_async16(uint32_t smem_dst, const void* gmem_src) {
    asm volatile("cp.async.cg.shared.global [%0], [%1], 16;\n" :: "r"(smem_dst), "l"(gmem_src));
}

// ---------------------------------------------------------------------------
// Pre-pass: fp32 -> fp16 ; transpose+cvt weights
// ---------------------------------------------------------------------------
__global__ void cvt_f32_h(const float4* __restrict__ in, __half2* __restrict__ out, int n4)
{
    for (int i = blockIdx.x * blockDim.x + threadIdx.x; i < n4; i += gridDim.x * blockDim.x) {
        float4 v = in[i];
        out[i * 2 + 0] = __floats2half2_rn(v.x, v.y);
        out[i * 2 + 1] = __floats2half2_rn(v.z, v.w);
    }
}

__global__ void transpose_h(const float* __restrict__ in, __half* __restrict__ out,
                            int K, int N)
{
    __shared__ float t[32][33];
    const int k0 = blockIdx.y * 32, n0 = blockIdx.x * 32;
    const int tx = threadIdx.x, ty = threadIdx.y;   // 32 x 8
    #pragma unroll
    for (int r = 0; r < 4; r++)
        t[ty + r * 8][tx] = in[(size_t)(k0 + ty + r * 8) * N + n0 + tx];
    __syncthreads();
    #pragma unroll
    for (int r = 0; r < 4; r++)
        out[(size_t)(n0 + ty + r * 8) * K + k0 + tx] = __float2half_rn(t[tx][ty + r * 8]);
}

// ---------------------------------------------------------------------------
// FP16 tensor-core GEMM: C[M,N] = A[M,K] @ Bt[N,K]^T + bias[N]   (fp32 accum)
// BM=128, BN=128, BK=64 halves (128B rows). 8 warps (2x4), warp tile 64x32.
// m16n8k16 HMMA, ldmatrix, 3-stage cp.async. KT = K/64 = 8 iterations.
// HALF_OUT: store __half. QSCALE: multiply cols<512 by 32^-0.5 (q pre-scale).
// ---------------------------------------------------------------------------
#define GBM 128
#define GBN 128
#define GBK 64
#define ROWH (GBK + 8)                     // 72 halves = 144B row stride
#define TILE_H (GBM * ROWH)                // 9216 halves per tile
#define STAGE_H (2 * TILE_H)               // A + B
#define GEMM_SMEM (3 * STAGE_H * 2)        // 110592 bytes

__device__ __forceinline__ void ldsm_x4(uint32_t addr, uint32_t& r0, uint32_t& r1,
                                        uint32_t& r2, uint32_t& r3) {
    asm volatile("ldmatrix.sync.aligned.m8n8.x4.shared.b16 {%0,%1,%2,%3}, [%4];"
                 : "=r"(r0), "=r"(r1), "=r"(r2), "=r"(r3) : "r"(addr));
}

template<bool HALF_OUT, bool QSCALE>
__global__ __launch_bounds__(256, 2)
void gemm_h(const __half* __restrict__ A, const __half* __restrict__ Bt,
            const float* __restrict__ bias, void* __restrict__ Cv,
            int M, int N, int K)
{
    extern __shared__ __half sm[];

    const int tid  = threadIdx.x;
    const int warp = tid >> 5;
    const int lane = tid & 31;
    const int wm = warp & 1;
    const int wn = warp >> 1;
    const int g  = lane >> 2;
    const int t  = lane & 3;

    const int cm = blockIdx.y * GBM;
    const int cn = blockIdx.x * GBN;

    // global->smem: 4 threads per row, each 32B (2x cp.async16), rows tid>>2 (+64)
    const int lrow = tid >> 2;             // 0..63
    const int lseg = (tid & 3) * 16;       // halves: 0,16,32,48

    const __half* Abase = A + (size_t)(cm + lrow) * K + lseg;
    const __half* Bbase = Bt + (size_t)(cn + lrow) * K + lseg;

    const uint32_t smb = smem_u32(sm);

    float acc[4][4][4];
    #pragma unroll
    for (int i = 0; i < 4; i++)
        #pragma unroll
        for (int j = 0; j < 4; j++)
            #pragma unroll
            for (int r = 0; r < 4; r++)
                acc[i][j][r] = 0.0f;

    const int KT = K / GBK;                // 8

    auto fill = [&](int kt, int st) {
        const int k0 = kt * GBK;
        #pragma unroll
        for (int r = 0; r < 2; r++) {
            const uint32_t sa = smb + (st * STAGE_H + (lrow + r * 64) * ROWH + lseg) * 2;
            const uint32_t sb = sa + TILE_H * 2;
            const __half* ap = Abase + (size_t)(r * 64) * K + k0;
            const __half* bp = Bbase + (size_t)(r * 64) * K + k0;
            cp_async16(sa,      ap);
            cp_async16(sa + 16, ap + 8);
            cp_async16(sb,      bp);
            cp_async16(sb + 16, bp + 8);
        }
        asm volatile("cp.async.commit_group;\n");
    };

    fill(0, 0);
    fill(1, 1);

    const int lgrp = lane >> 3;
    const int lr   = lane & 7;
    const int a_row_add = (lgrp & 1) * 8 + lr;
    const int a_k_add   = (lgrp & 2) * 4;
    const int b_row_add = (lgrp >> 1) * 8 + lr;
    const int b_k_add   = (lgrp & 1) * 8;

    for (int kt = 0; kt < KT; kt++) {
        const int st = kt % 3;
        if (kt == KT - 1) {
            asm volatile("cp.async.wait_group 0;\n");
        } else {
            asm volatile("cp.async.wait_group 1;\n");
        }
        __syncthreads();

        if (kt + 2 < KT) fill(kt + 2, (kt + 2) % 3);

        const uint32_t sa = smb + (st * STAGE_H) * 2;
        const uint32_t sb = sa + TILE_H * 2;

        #pragma unroll
        for (int ks = 0; ks < 4; ks++) {
            const int k16 = ks * 16;
            uint32_t af[4][4];
            #pragma unroll
            for (int mt = 0; mt < 4; mt++) {
                const int row = wm * 64 + mt * 16 + a_row_add;
                ldsm_x4(sa + (row * ROWH + k16 + a_k_add) * 2,
                        af[mt][0], af[mt][1], af[mt][2], af[mt][3]);
            }
            uint32_t bf[4][2];
            #pragma unroll
            for (int np = 0; np < 2; np++) {
                const int row = wn * 32 + np * 16 + b_row_add;
                ldsm_x4(sb + (row * ROWH + k16 + b_k_add) * 2,
                        bf[np * 2][0], bf[np * 2][1], bf[np * 2 + 1][0], bf[np * 2 + 1][1]);
            }
            #pragma unroll
            for (int mt = 0; mt < 4; mt++)
                #pragma unroll
                for (int nt = 0; nt < 4; nt++) {
                    asm volatile(
                        "mma.sync.aligned.m16n8k16.row.col.f32.f16.f16.f32 "
                        "{%0,%1,%2,%3}, {%4,%5,%6,%7}, {%8,%9}, {%0,%1,%2,%3};\n"
                        : "+f"(acc[mt][nt][0]), "+f"(acc[mt][nt][1]),
                          "+f"(acc[mt][nt][2]), "+f"(acc[mt][nt][3])
                        : "r"(af[mt][0]), "r"(af[mt][1]), "r"(af[mt][2]), "r"(af[mt][3]),
                          "r"(bf[nt][0]), "r"(bf[nt][1]));
                }
        }
        __syncthreads();
    }

    // epilogue
    #pragma unroll
    for (int mt = 0; mt < 4; mt++) {
        const size_t r0 = (size_t)cm + wm * 64 + mt * 16 + g;
        #pragma unroll
        for (int nt = 0; nt < 4; nt++) {
            const int col = cn + wn * 32 + nt * 8 + 2 * t;
            const float2 bv = *reinterpret_cast<const float2*>(bias + col);
            float sc = 1.0f;
            if (QSCALE) sc = (col < 512) ? 0.17677669529663687f : 1.0f;
            float2 o0, o1;
            o0.x = (acc[mt][nt][0] + bv.x) * sc;
            o0.y = (acc[mt][nt][1] + bv.y) * sc;
            o1.x = (acc[mt][nt][2] + bv.x) * sc;
            o1.y = (acc[mt][nt][3] + bv.y) * sc;
            if (HALF_OUT) {
                __half* C = (__half*)Cv;
                *reinterpret_cast<__half2*>(C + r0 * N + col) = __floats2half2_rn(o0.x, o0.y);
                *reinterpret_cast<__half2*>(C + (r0 + 8) * N + col) = __floats2half2_rn(o1.x, o1.y);
            } else {
                float* C = (float*)Cv;
                *reinterpret_cast<float2*>(C + r0 * N + col)       = o0;
                *reinterpret_cast<float2*>(C + (r0 + 8) * N + col) = o1;
            }
        }
    }
}

// ---------------------------------------------------------------------------
// Attention: one block per (window b, head h), 64 threads.
// Reads fp16 qkv (q pre-scaled), fp32 math, writes fp16 out.
// ---------------------------------------------------------------------------
#define PADW 36

__global__ __launch_bounds__(64)
void attn_kernel(const float* __restrict__ rel)
{
    const int b = blockIdx.x;
    const int h = blockIdx.y;
    const int tid = threadIdx.x;

    __shared__ float qs[N_TOK][PADW];
    __shared__ float ks[N_TOK][PADW];
    __shared__ float vs[N_TOK][PADW];
    __shared__ __half os[N_TOK][DH];
    __shared__ float rels[REL_SZ * REL_SZ];

    const __half* gq = g_qkvh + (size_t)b * N_TOK * QKV_DIM + h * DH;

    // 64 rows x 32 halves = 256 chunks of 8 halves per matrix
    for (int idx = tid; idx < N_TOK * 4; idx += 64) {
        const int m = idx >> 2;
        const int c = (idx & 3) * 8;
        const __half* p = gq + (size_t)m * QKV_DIM + c;
        const __half2* q2 = reinterpret_cast<const __half2*>(p);
        const __half2* k2 = reinterpret_cast<const __half2*>(p + 512);
        const __half2* v2 = reinterpret_cast<const __half2*>(p + 1024);
        #pragma unroll
        for (int u = 0; u < 4; u++) {
            float2 qv = __half22float2(q2[u]);
            float2 kv = __half22float2(k2[u]);
            float2 vv = __half22float2(v2[u]);
            qs[m][c + 2 * u] = qv.x; qs[m][c + 2 * u + 1] = qv.y;
            ks[m][c + 2 * u] = kv.x; ks[m][c + 2 * u + 1] = kv.y;
            vs[m][c + 2 * u] = vv.x; vs[m][c + 2 * u + 1] = vv.y;
        }
    }
    for (int p = tid; p < REL_SZ * REL_SZ; p += 64) rels[p] = rel[h * REL_SZ * REL_SZ + p];
    __syncthreads();

    const int i = tid;
    float q[DH];
    #pragma unroll
    for (int d = 0; d < DH; d++) q[d] = qs[i][d];   // already scaled

    const int yi = i >> 3, xi = i & 7;

    float sc[N_TOK];
    float mx = -1e30f;
    #pragma unroll
    for (int j = 0; j < N_TOK; j++) {
        float s0 = 0.f, s1 = 0.f, s2 = 0.f, s3 = 0.f;
        #pragma unroll
        for (int d = 0; d < DH; d += 4) {
            const float4 kk = *reinterpret_cast<const float4*>(&ks[j][d]);
            s0 = fmaf(q[d + 0], kk.x, s0);
            s1 = fmaf(q[d + 1], kk.y, s1);
            s2 = fmaf(q[d + 2], kk.z, s2);
            s3 = fmaf(q[d + 3], kk.w, s3);
        }
        const int yj = j >> 3, xj = j & 7;
        const float s = (s0 + s1) + (s2 + s3) + rels[(yi - yj + 7) * REL_SZ + (xi - xj + 7)];
        sc[j] = s;
        mx = fmaxf(mx, s);
    }

    float sum = 0.0f;
    #pragma unroll
    for (int j = 0; j < N_TOK; j++) {
        const float e = __expf(sc[j] - mx);
        sc[j] = e;
        sum += e;
    }
    const float inv = 1.0f / sum;

    float out[DH];
    #pragma unroll
    for (int d = 0; d < DH; d++) out[d] = 0.0f;
    #pragma unroll
    for (int j = 0; j < N_TOK; j++) {
        const float p = sc[j];
        #pragma unroll
        for (int d = 0; d < DH; d += 4) {
            const float4 vv = *reinterpret_cast<const float4*>(&vs[j][d]);
            out[d + 0] = fmaf(p, vv.x, out[d + 0]);
            out[d + 1] = fmaf(p, vv.y, out[d + 1]);
            out[d + 2] = fmaf(p, vv.z, out[d + 2]);
            out[d + 3] = fmaf(p, vv.w, out[d + 3]);
        }
    }

    #pragma unroll
    for (int d = 0; d < DH; d += 2)
        *reinterpret_cast<__half2*>(&os[i][d]) =
            __floats2half2_rn(out[d] * inv, out[d + 1] * inv);
    __syncthreads();

    __half* go = g_atth + (size_t)b * N_TOK * DIM + h * DH;
    for (int idx = tid; idx < N_TOK * 4; idx += 64) {
        const int m = idx >> 2;
        const int c = (idx & 3) * 8;
        *reinterpret_cast<uint4*>(go + (size_t)m * DIM + c) =
            *reinterpret_cast<const uint4*>(&os[m][c]);
    }
}

// ---------------------------------------------------------------------------
// Launch
// ---------------------------------------------------------------------------
extern "C" void kernel_launch(void* const* d_in, const int* in_sizes, int n_in,
                              void* d_out, int out_size)
{
    const float* x      = (const float*)d_in[0];
    const float* w_qkv  = (const float*)d_in[1];
    const float* b_qkv  = (const float*)d_in[2];
    const float* rel    = (const float*)d_in[3];
    const float* w_proj = (const float*)d_in[4];
    const float* b_proj = (const float*)d_in[5];
    float* out = (float*)d_out;
    (void)in_sizes; (void)n_in; (void)out_size;

    __half *qkvh, *xh, *atth, *wqkvt, *wprojt;
    cudaGetSymbolAddress((void**)&qkvh,   g_qkvh);
    cudaGetSymbolAddress((void**)&xh,     g_xh);
    cudaGetSymbolAddress((void**)&atth,   g_atth);
    cudaGetSymbolAddress((void**)&wqkvt,  g_wqkv_t);
    cudaGetSymbolAddress((void**)&wprojt, g_wproj_t);

    cudaFuncSetAttribute(gemm_h<true, true>,   cudaFuncAttributeMaxDynamicSharedMemorySize, GEMM_SMEM);
    cudaFuncSetAttribute(gemm_h<false, false>, cudaFuncAttributeMaxDynamicSharedMemorySize, GEMM_SMEM);

    // 0) Convert x to fp16; transpose+convert weights to [N,K] fp16
    cvt_f32_h<<<4096, 256>>>((const float4*)x, (__half2*)xh, (M_ROWS * DIM) / 4);
    {
        dim3 blk(32, 8);
        transpose_h<<<dim3(QKV_DIM / 32, DIM / 32), blk>>>(w_qkv, wqkvt, DIM, QKV_DIM);
        transpose_h<<<dim3(DIM / 32, DIM / 32),     blk>>>(w_proj, wprojt, DIM, DIM);
    }

    // 1) QKV GEMM -> fp16, q pre-scaled
    {
        dim3 grid(QKV_DIM / GBN, M_ROWS / GBM);   // (12, 1024)
        gemm_h<true, true><<<grid, 256, GEMM_SMEM>>>(xh, wqkvt, b_qkv, qkvh,
                                                     M_ROWS, QKV_DIM, DIM);
    }

    // 2) Windowed attention
    {
        dim3 grid(B_WIN, HEADS);
        attn_kernel<<<grid, 64>>>(rel);
    }

    // 3) Output projection -> fp32
    {
        dim3 grid(DIM / GBN, M_ROWS / GBM);       // (4, 1024)
        gemm_h<false, false><<<grid, 256, GEMM_SMEM>>>(atth, wprojt, b_proj, out,
                                                       M_ROWS, DIM, DIM);
    }
}

// round 8
// speedup vs baseline: 2.4713x; 1.5036x over previous
#include <cuda_runtime.h>
#include <cuda_fp16.h>
#include <math.h>
#include <stdint.h>

// Problem constants
#define B_WIN   2048
#define N_TOK   64
#define DIM     512
#define HEADS   16
#define DH      32
#define QKV_DIM 1536
#define WIN     8
#define REL_SZ  15
#define M_ROWS  (B_WIN * N_TOK)   // 131072

// Scratch (no cudaMalloc allowed)
__device__ __half g_qkvh[(size_t)M_ROWS * QKV_DIM];    // qkv, fp16 (q pre-scaled)
__device__ __half g_xh[(size_t)M_ROWS * DIM];          // x, fp16
__device__ __half g_atth[(size_t)M_ROWS * DIM];        // attention out, fp16
__device__ __half g_wqkv_t[(size_t)QKV_DIM * DIM];     // w_qkv^T [N,K], fp16
__device__ __half g_wproj_t[(size_t)DIM * DIM];        // w_proj^T [N,K], fp16

__device__ __forceinline__ uint32_t smem_u32(const void* p) {
    uint32_t a;
    asm("{ .reg .u64 t; cvta.to.shared.u64 t, %1; cvt.u32.u64 %0, t; }" : "=r"(a) : "l"(p));
    return a;
}

__device__ __forceinline__ void cp_async16(uint32_t smem_dst, const void* gmem_src) {
    asm volatile("cp.async.cg.shared.global [%0], [%1], 16;\n" :: "r"(smem_dst), "l"(gmem_src));
}

__device__ __forceinline__ void ldsm_x4(uint32_t addr, uint32_t& r0, uint32_t& r1,
                                        uint32_t& r2, uint32_t& r3) {
    asm volatile("ldmatrix.sync.aligned.m8n8.x4.shared.b16 {%0,%1,%2,%3}, [%4];"
                 : "=r"(r0), "=r"(r1), "=r"(r2), "=r"(r3) : "r"(addr));
}

__device__ __forceinline__ void ldsm_x4_t(uint32_t addr, uint32_t& r0, uint32_t& r1,
                                          uint32_t& r2, uint32_t& r3) {
    asm volatile("ldmatrix.sync.aligned.m8n8.x4.trans.shared.b16 {%0,%1,%2,%3}, [%4];"
                 : "=r"(r0), "=r"(r1), "=r"(r2), "=r"(r3) : "r"(addr));
}

__device__ __forceinline__ void hmma(float* c, const uint32_t* a, const uint32_t* b) {
    asm volatile(
        "mma.sync.aligned.m16n8k16.row.col.f32.f16.f16.f32 "
        "{%0,%1,%2,%3}, {%4,%5,%6,%7}, {%8,%9}, {%0,%1,%2,%3};\n"
        : "+f"(c[0]), "+f"(c[1]), "+f"(c[2]), "+f"(c[3])
        : "r"(a[0]), "r"(a[1]), "r"(a[2]), "r"(a[3]), "r"(b[0]), "r"(b[1]));
}

// ---------------------------------------------------------------------------
// Pre-pass: fp32 -> fp16 ; transpose+cvt weights
// ---------------------------------------------------------------------------
__global__ void cvt_f32_h(const float4* __restrict__ in, __half2* __restrict__ out, int n4)
{
    for (int i = blockIdx.x * blockDim.x + threadIdx.x; i < n4; i += gridDim.x * blockDim.x) {
        float4 v = in[i];
        out[i * 2 + 0] = __floats2half2_rn(v.x, v.y);
        out[i * 2 + 1] = __floats2half2_rn(v.z, v.w);
    }
}

__global__ void transpose_h(const float* __restrict__ in, __half* __restrict__ out,
                            int K, int N)
{
    __shared__ float t[32][33];
    const int k0 = blockIdx.y * 32, n0 = blockIdx.x * 32;
    const int tx = threadIdx.x, ty = threadIdx.y;   // 32 x 8
    #pragma unroll
    for (int r = 0; r < 4; r++)
        t[ty + r * 8][tx] = in[(size_t)(k0 + ty + r * 8) * N + n0 + tx];
    __syncthreads();
    #pragma unroll
    for (int r = 0; r < 4; r++)
        out[(size_t)(n0 + ty + r * 8) * K + k0 + tx] = __float2half_rn(t[tx][ty + r * 8]);
}

// ---------------------------------------------------------------------------
// FP16 tensor-core GEMM (unchanged from round 7)
// ---------------------------------------------------------------------------
#define GBM 128
#define GBN 128
#define GBK 64
#define ROWH (GBK + 8)
#define TILE_H (GBM * ROWH)
#define STAGE_H (2 * TILE_H)
#define GEMM_SMEM (3 * STAGE_H * 2)

template<bool HALF_OUT, bool QSCALE>
__global__ __launch_bounds__(256, 2)
void gemm_h(const __half* __restrict__ A, const __half* __restrict__ Bt,
            const float* __restrict__ bias, void* __restrict__ Cv,
            int M, int N, int K)
{
    extern __shared__ __half sm[];

    const int tid  = threadIdx.x;
    const int warp = tid >> 5;
    const int lane = tid & 31;
    const int wm = warp & 1;
    const int wn = warp >> 1;
    const int g  = lane >> 2;
    const int t  = lane & 3;

    const int cm = blockIdx.y * GBM;
    const int cn = blockIdx.x * GBN;

    const int lrow = tid >> 2;
    const int lseg = (tid & 3) * 16;

    const __half* Abase = A + (size_t)(cm + lrow) * K + lseg;
    const __half* Bbase = Bt + (size_t)(cn + lrow) * K + lseg;

    const uint32_t smb = smem_u32(sm);

    float acc[4][4][4];
    #pragma unroll
    for (int i = 0; i < 4; i++)
        #pragma unroll
        for (int j = 0; j < 4; j++)
            #pragma unroll
            for (int r = 0; r < 4; r++)
                acc[i][j][r] = 0.0f;

    const int KT = K / GBK;

    auto fill = [&](int kt, int st) {
        const int k0 = kt * GBK;
        #pragma unroll
        for (int r = 0; r < 2; r++) {
            const uint32_t sa = smb + (st * STAGE_H + (lrow + r * 64) * ROWH + lseg) * 2;
            const uint32_t sb = sa + TILE_H * 2;
            const __half* ap = Abase + (size_t)(r * 64) * K + k0;
            const __half* bp = Bbase + (size_t)(r * 64) * K + k0;
            cp_async16(sa,      ap);
            cp_async16(sa + 16, ap + 8);
            cp_async16(sb,      bp);
            cp_async16(sb + 16, bp + 8);
        }
        asm volatile("cp.async.commit_group;\n");
    };

    fill(0, 0);
    fill(1, 1);

    const int lgrp = lane >> 3;
    const int lr   = lane & 7;
    const int a_row_add = (lgrp & 1) * 8 + lr;
    const int a_k_add   = (lgrp & 2) * 4;
    const int b_row_add = (lgrp >> 1) * 8 + lr;
    const int b_k_add   = (lgrp & 1) * 8;

    for (int kt = 0; kt < KT; kt++) {
        const int st = kt % 3;
        if (kt == KT - 1) {
            asm volatile("cp.async.wait_group 0;\n");
        } else {
            asm volatile("cp.async.wait_group 1;\n");
        }
        __syncthreads();

        if (kt + 2 < KT) fill(kt + 2, (kt + 2) % 3);

        const uint32_t sa = smb + (st * STAGE_H) * 2;
        const uint32_t sb = sa + TILE_H * 2;

        #pragma unroll
        for (int ks = 0; ks < 4; ks++) {
            const int k16 = ks * 16;
            uint32_t af[4][4];
            #pragma unroll
            for (int mt = 0; mt < 4; mt++) {
                const int row = wm * 64 + mt * 16 + a_row_add;
                ldsm_x4(sa + (row * ROWH + k16 + a_k_add) * 2,
                        af[mt][0], af[mt][1], af[mt][2], af[mt][3]);
            }
            uint32_t bf[4][2];
            #pragma unroll
            for (int np = 0; np < 2; np++) {
                const int row = wn * 32 + np * 16 + b_row_add;
                ldsm_x4(sb + (row * ROWH + k16 + b_k_add) * 2,
                        bf[np * 2][0], bf[np * 2][1], bf[np * 2 + 1][0], bf[np * 2 + 1][1]);
            }
            #pragma unroll
            for (int mt = 0; mt < 4; mt++)
                #pragma unroll
                for (int nt = 0; nt < 4; nt++)
                    hmma(acc[mt][nt], af[mt], bf[nt]);
        }
        __syncthreads();
    }

    #pragma unroll
    for (int mt = 0; mt < 4; mt++) {
        const size_t r0 = (size_t)cm + wm * 64 + mt * 16 + g;
        #pragma unroll
        for (int nt = 0; nt < 4; nt++) {
            const int col = cn + wn * 32 + nt * 8 + 2 * t;
            const float2 bv = *reinterpret_cast<const float2*>(bias + col);
            float sc = 1.0f;
            if (QSCALE) sc = (col < 512) ? 0.17677669529663687f : 1.0f;
            float2 o0, o1;
            o0.x = (acc[mt][nt][0] + bv.x) * sc;
            o0.y = (acc[mt][nt][1] + bv.y) * sc;
            o1.x = (acc[mt][nt][2] + bv.x) * sc;
            o1.y = (acc[mt][nt][3] + bv.y) * sc;
            if (HALF_OUT) {
                __half* C = (__half*)Cv;
                *reinterpret_cast<__half2*>(C + r0 * N + col) = __floats2half2_rn(o0.x, o0.y);
                *reinterpret_cast<__half2*>(C + (r0 + 8) * N + col) = __floats2half2_rn(o1.x, o1.y);
            } else {
                float* C = (float*)Cv;
                *reinterpret_cast<float2*>(C + r0 * N + col)       = o0;
                *reinterpret_cast<float2*>(C + (r0 + 8) * N + col) = o1;
            }
        }
    }
}

// ---------------------------------------------------------------------------
// Tensor-core attention: one block per (b,h), 4 warps, warp = 16 query rows.
// Scores via HMMA, softmax in accumulator registers, P kept in registers as
// A-fragments, PV via HMMA with ldmatrix.trans B-frags.
// ---------------------------------------------------------------------------
#define QKPAD 40   // half row stride (80B) for Q/K/V smem tiles

__global__ __launch_bounds__(128)
void attn_tc(const float* __restrict__ rel)
{
    const int b = blockIdx.x;
    const int h = blockIdx.y;
    const int tid  = threadIdx.x;
    const int warp = tid >> 5;
    const int lane = tid & 31;
    const int g = lane >> 2;
    const int t = lane & 3;
    const int lgrp = lane >> 3;
    const int lr   = lane & 7;

    __shared__ __half Qs[N_TOK][QKPAD];
    __shared__ __half Ks[N_TOK][QKPAD];
    __shared__ __half Vs[N_TOK][QKPAD];
    __shared__ float rels[REL_SZ * REL_SZ + 1];

    const __half* gq = g_qkvh + (size_t)b * N_TOK * QKV_DIM + h * DH;

    // stage Q/K/V (fp16, q pre-scaled): 64 rows x 32 halves = 256 x 8-half chunks
    for (int idx = tid; idx < N_TOK * 4; idx += 128) {
        const int m = idx >> 2;
        const int c = (idx & 3) * 8;
        const __half* p = gq + (size_t)m * QKV_DIM + c;
        *reinterpret_cast<uint4*>(&Qs[m][c]) = *reinterpret_cast<const uint4*>(p);
        *reinterpret_cast<uint4*>(&Ks[m][c]) = *reinterpret_cast<const uint4*>(p + 512);
        *reinterpret_cast<uint4*>(&Vs[m][c]) = *reinterpret_cast<const uint4*>(p + 1024);
    }
    for (int p = tid; p < REL_SZ * REL_SZ; p += 128) rels[p] = rel[h * REL_SZ * REL_SZ + p];
    __syncthreads();

    const uint32_t qb = smem_u32(&Qs[0][0]);
    const uint32_t kb = smem_u32(&Ks[0][0]);
    const uint32_t vb = smem_u32(&Vs[0][0]);

    const int a_row = warp * 16 + (lgrp & 1) * 8 + lr;
    const int a_kad = (lgrp & 2) * 4;
    const int b_rad = (lgrp >> 1) * 8 + lr;
    const int b_kad = (lgrp & 1) * 8;

    // ---- scores: S = Q(16x32) @ K^T(32x64) per warp ----
    float acc[8][4];
    #pragma unroll
    for (int nt = 0; nt < 8; nt++)
        #pragma unroll
        for (int r = 0; r < 4; r++) acc[nt][r] = 0.0f;

    #pragma unroll
    for (int kc = 0; kc < 2; kc++) {
        const int k16 = kc * 16;
        uint32_t af[4];
        ldsm_x4(qb + (a_row * QKPAD + k16 + a_kad) * 2, af[0], af[1], af[2], af[3]);
        uint32_t bf[8][2];
        #pragma unroll
        for (int np = 0; np < 4; np++) {
            const int row = np * 16 + b_rad;
            ldsm_x4(kb + (row * QKPAD + k16 + b_kad) * 2,
                    bf[np * 2][0], bf[np * 2][1], bf[np * 2 + 1][0], bf[np * 2 + 1][1]);
        }
        #pragma unroll
        for (int nt = 0; nt < 8; nt++) hmma(acc[nt], af, bf[nt]);
    }

    // ---- add relative-position bias ----
    // rows: i0 = warp*16+g, i1 = i0+8 ; cols: j = nt*8 + 2t (+1) -> yj=nt, xj=2t(+1)
    const int i0 = warp * 16 + g;
    const int yi0 = i0 >> 3, xi0 = i0 & 7;
    const int base0 = (yi0 + 7) * REL_SZ + xi0 - 2 * t + 7;  // row i0, col 2t, nt=0
    const int base1 = base0 + REL_SZ;                        // row i1 (yi0+1)
    #pragma unroll
    for (int nt = 0; nt < 8; nt++) {
        const int o = nt * REL_SZ;
        acc[nt][0] += rels[base0 - o];
        acc[nt][1] += rels[base0 - o - 1];
        acc[nt][2] += rels[base1 - o];
        acc[nt][3] += rels[base1 - o - 1];
    }

    // ---- softmax (rows span 4 lanes: reduce via shfl.bfly 1,2) ----
    float mx0 = -1e30f, mx1 = -1e30f;
    #pragma unroll
    for (int nt = 0; nt < 8; nt++) {
        mx0 = fmaxf(mx0, fmaxf(acc[nt][0], acc[nt][1]));
        mx1 = fmaxf(mx1, fmaxf(acc[nt][2], acc[nt][3]));
    }
    mx0 = fmaxf(mx0, __shfl_xor_sync(0xffffffffu, mx0, 1));
    mx0 = fmaxf(mx0, __shfl_xor_sync(0xffffffffu, mx0, 2));
    mx1 = fmaxf(mx1, __shfl_xor_sync(0xffffffffu, mx1, 1));
    mx1 = fmaxf(mx1, __shfl_xor_sync(0xffffffffu, mx1, 2));

    float sum0 = 0.0f, sum1 = 0.0f;
    #pragma unroll
    for (int nt = 0; nt < 8; nt++) {
        acc[nt][0] = __expf(acc[nt][0] - mx0);
        acc[nt][1] = __expf(acc[nt][1] - mx0);
        acc[nt][2] = __expf(acc[nt][2] - mx1);
        acc[nt][3] = __expf(acc[nt][3] - mx1);
        sum0 += acc[nt][0] + acc[nt][1];
        sum1 += acc[nt][2] + acc[nt][3];
    }
    sum0 += __shfl_xor_sync(0xffffffffu, sum0, 1);
    sum0 += __shfl_xor_sync(0xffffffffu, sum0, 2);
    sum1 += __shfl_xor_sync(0xffffffffu, sum1, 1);
    sum1 += __shfl_xor_sync(0xffffffffu, sum1, 2);
    const float inv0 = 1.0f / sum0;
    const float inv1 = 1.0f / sum1;

    // ---- convert P to A-fragments (acc n-tile pair -> A k-chunk) ----
    uint32_t pa[4][4];
    #pragma unroll
    for (int kc = 0; kc < 4; kc++) {
        __half2 h0 = __floats2half2_rn(acc[2 * kc][0] * inv0,     acc[2 * kc][1] * inv0);
        __half2 h1 = __floats2half2_rn(acc[2 * kc][2] * inv1,     acc[2 * kc][3] * inv1);
        __half2 h2 = __floats2half2_rn(acc[2 * kc + 1][0] * inv0, acc[2 * kc + 1][1] * inv0);
        __half2 h3 = __floats2half2_rn(acc[2 * kc + 1][2] * inv1, acc[2 * kc + 1][3] * inv1);
        pa[kc][0] = *reinterpret_cast<uint32_t*>(&h0);
        pa[kc][1] = *reinterpret_cast<uint32_t*>(&h1);
        pa[kc][2] = *reinterpret_cast<uint32_t*>(&h2);
        pa[kc][3] = *reinterpret_cast<uint32_t*>(&h3);
    }

    // ---- O = P(16x64) @ V(64x32) per warp ----
    float out[4][4];
    #pragma unroll
    for (int nt = 0; nt < 4; nt++)
        #pragma unroll
        for (int r = 0; r < 4; r++) out[nt][r] = 0.0f;

    #pragma unroll
    for (int kc = 0; kc < 4; kc++) {
        uint32_t vf[4][2];
        #pragma unroll
        for (int nh = 0; nh < 2; nh++) {
            // trans load: B[k][n] frag from row-major Vs[j=k][d=n]
            const int row = kc * 16 + (lgrp & 1) * 8 + lr;
            const int col = nh * 16 + (lgrp >> 1) * 8;
            ldsm_x4_t(vb + (row * QKPAD + col) * 2,
                      vf[nh * 2][0], vf[nh * 2][1], vf[nh * 2 + 1][0], vf[nh * 2 + 1][1]);
        }
        #pragma unroll
        for (int nt = 0; nt < 4; nt++) hmma(out[nt], pa[kc], vf[nt]);
    }

    // ---- store fp16 output ----
    __half* go = g_atth + (size_t)b * N_TOK * DIM + h * DH;
    const int r0 = warp * 16 + g;
    #pragma unroll
    for (int nt = 0; nt < 4; nt++) {
        const int col = nt * 8 + 2 * t;
        *reinterpret_cast<__half2*>(go + (size_t)r0 * DIM + col) =
            __floats2half2_rn(out[nt][0], out[nt][1]);
        *reinterpret_cast<__half2*>(go + (size_t)(r0 + 8) * DIM + col) =
            __floats2half2_rn(out[nt][2], out[nt][3]);
    }
}

// ---------------------------------------------------------------------------
// Launch
// ---------------------------------------------------------------------------
extern "C" void kernel_launch(void* const* d_in, const int* in_sizes, int n_in,
                              void* d_out, int out_size)
{
    const float* x      = (const float*)d_in[0];
    const float* w_qkv  = (const float*)d_in[1];
    const float* b_qkv  = (const float*)d_in[2];
    const float* rel    = (const float*)d_in[3];
    const float* w_proj = (const float*)d_in[4];
    const float* b_proj = (const float*)d_in[5];
    float* out = (float*)d_out;
    (void)in_sizes; (void)n_in; (void)out_size;

    __half *qkvh, *xh, *atth, *wqkvt, *wprojt;
    cudaGetSymbolAddress((void**)&qkvh,   g_qkvh);
    cudaGetSymbolAddress((void**)&xh,     g_xh);
    cudaGetSymbolAddress((void**)&atth,   g_atth);
    cudaGetSymbolAddress((void**)&wqkvt,  g_wqkv_t);
    cudaGetSymbolAddress((void**)&wprojt, g_wproj_t);

    cudaFuncSetAttribute(gemm_h<true, true>,   cudaFuncAttributeMaxDynamicSharedMemorySize, GEMM_SMEM);
    cudaFuncSetAttribute(gemm_h<false, false>, cudaFuncAttributeMaxDynamicSharedMemorySize, GEMM_SMEM);

    // 0) Convert x to fp16; transpose+convert weights to [N,K] fp16
    cvt_f32_h<<<4096, 256>>>((const float4*)x, (__half2*)xh, (M_ROWS * DIM) / 4);
    {
        dim3 blk(32, 8);
        transpose_h<<<dim3(QKV_DIM / 32, DIM / 32), blk>>>(w_qkv, wqkvt, DIM, QKV_DIM);
        transpose_h<<<dim3(DIM / 32, DIM / 32),     blk>>>(w_proj, wprojt, DIM, DIM);
    }

    // 1) QKV GEMM -> fp16, q pre-scaled
    {
        dim3 grid(QKV_DIM / GBN, M_ROWS / GBM);   // (12, 1024)
        gemm_h<true, true><<<grid, 256, GEMM_SMEM>>>(xh, wqkvt, b_qkv, qkvh,
                                                     M_ROWS, QKV_DIM, DIM);
    }

    // 2) Windowed attention (tensor cores)
    {
        dim3 grid(B_WIN, HEADS);
        attn_tc<<<grid, 128>>>(rel);
    }

    // 3) Output projection -> fp32
    {
        dim3 grid(DIM / GBN, M_ROWS / GBM);       // (4, 1024)
        gemm_h<false, false><<<grid, 256, GEMM_SMEM>>>(atth, wprojt, b_proj, out,
                                                       M_ROWS, DIM, DIM);
    }
}